// round 11
// baseline (speedup 1.0000x reference)
#include <cuda_runtime.h>
#include <cuda_bf16.h>
#include <math.h>

#define NN 50000
#define EE 600000
#define ET (EE + NN)
#define SCAN_CHUNK 1024
#define NB_SCAN ((NN + SCAN_CHUNK - 1) / SCAN_CHUNK)   // 49
#define FLAG_AGG  (1 << 30)
#define FLAG_INC  (1u << 31)
#define FLAG_MASK ((1 << 30) - 1)

// ---------------- scratch (module-load zeroed; invariants restored per call) --
__device__ int g_cnt[NN];
__device__ int g_cur[NN];
__device__ int g_off[NN + 1];
__device__ int g_flagw[NB_SCAN];
__device__ int g_srcs[ET];
__device__ __align__(16) float g_h1[(size_t)NN * 128];
__device__ __align__(16) float g_x2[(size_t)NN * 128];
__device__ __align__(16) float g_h2[(size_t)NN * 128];
__device__ __align__(16) float g_als1[NN * 4];
__device__ __align__(16) float g_ald1[NN * 4];
__device__ float g_als2[NN];
__device__ float g_ald2[NN];

__device__ __forceinline__ int load_idx(const void* p, size_t i, int is64) {
    if (is64) return (int)((const long long*)p)[i];
    return ((const int*)p)[i];
}

__device__ __forceinline__ int detect_is64_block(const long long* ei64, int e) {
    __shared__ int s_ok;
    if (threadIdx.x == 0) s_ok = 1;
    __syncthreads();
    if (threadIdx.x < 64) {
        long long v = ei64[threadIdx.x];
        long long v2 = ei64[(size_t)e + threadIdx.x];
        if (v < 0 || v >= NN || v2 < 0 || v2 >= NN) s_ok = 0;
    }
    __syncthreads();
    return s_ok;
}

// ---------------- f32x2 helpers ----------------
__device__ __forceinline__ unsigned long long pack2(float lo, float hi) {
    unsigned long long r;
    asm("mov.b64 %0, {%1, %2};" : "=l"(r) : "f"(lo), "f"(hi));
    return r;
}
__device__ __forceinline__ void fma2(unsigned long long& d, unsigned long long a,
                                     unsigned long long b) {
    asm("fma.rn.f32x2 %0, %1, %2, %0;" : "+l"(d) : "l"(a), "l"(b));
}

// ---------------- CSR: histogram (also clears scan flags) ----------
__global__ void hist_kernel(const void* __restrict__ ei, int e) {
    if (blockIdx.x < NB_SCAN && threadIdx.x == 0) g_flagw[blockIdx.x] = 0;
    int is64 = detect_is64_block((const long long*)ei, e);
    int i = blockIdx.x * blockDim.x + threadIdx.x;
    if (i < e) {
        int d = load_idx(ei, (size_t)e + i, is64);
        if (d >= 0 && d < NN) atomicAdd(&g_cnt[d], 1);
    }
}

// ---------------- CSR: single-pass decoupled-lookback scan -------------------
__global__ void __launch_bounds__(256) scan_kernel(int n, int nb) {
    int b = blockIdx.x, tid = threadIdx.x;
    int lane = tid & 31, wid = tid >> 5;
    int base = b * SCAN_CHUNK + tid * 4;
    int v[4];
    int tsum = 0;
#pragma unroll
    for (int k = 0; k < 4; k++) {
        int i = base + k;
        if (i < n) {
            v[k] = g_cnt[i] + 1;
            g_cnt[i] = 0;
            g_cur[i] = 0;
        } else v[k] = 0;
        tsum += v[k];
    }
    const unsigned FULL = 0xffffffffu;
    int x = tsum;
#pragma unroll
    for (int o = 1; o < 32; o <<= 1) {
        int y = __shfl_up_sync(FULL, x, o);
        if (lane >= o) x += y;
    }
    __shared__ int wsum[8];
    if (lane == 31) wsum[wid] = x;
    __syncthreads();
    __shared__ int s_excl;
    if (tid == 0) {
        int tot = 0;
#pragma unroll
        for (int w = 0; w < 8; w++) tot += wsum[w];
        if (b == 0) {
            *(volatile int*)&g_flagw[0] = tot | FLAG_INC;
            s_excl = 0;
            if (nb == 1) g_off[n] = tot;
        } else {
            *(volatile int*)&g_flagw[b] = (tot & FLAG_MASK) | FLAG_AGG;
            int excl = 0;
            for (int j = b - 1; j >= 0;) {
                int f;
                do { f = *(volatile int*)&g_flagw[j]; } while (f == 0);
                if (f & FLAG_INC) { excl += f & FLAG_MASK; break; }
                excl += f & FLAG_MASK;
                j--;
            }
            *(volatile int*)&g_flagw[b] = ((excl + tot) & FLAG_MASK) | FLAG_INC;
            s_excl = excl;
            if (b == nb - 1) g_off[n] = excl + tot;
        }
    }
    __syncthreads();
    int wpre = 0;
    for (int w = 0; w < wid; w++) wpre += wsum[w];
    int run = s_excl + wpre + (x - tsum);
#pragma unroll
    for (int k = 0; k < 4; k++) {
        int i = base + k;
        if (i < n) g_off[i] = run;
        run += v[k];
    }
}

// ---------------- CSR: scatter ----------------
__global__ void scatter_kernel(const void* __restrict__ ei, int e, int n) {
    int is64 = detect_is64_block((const long long*)ei, e);
    int i = blockIdx.x * blockDim.x + threadIdx.x;
    if (i < e) {
        int d = load_idx(ei, (size_t)e + i, is64);
        int s = load_idx(ei, (size_t)i, is64);
        if (d >= 0 && d < NN && s >= 0 && s < NN) {
            int pos = g_off[d] + atomicAdd(&g_cur[d], 1);
            g_srcs[pos] = s;
        }
    } else if (i < e + n) {
        int v = i - e;
        int pos = g_off[v] + atomicAdd(&g_cur[v], 1);
        g_srcs[pos] = v;
    }
}

// ---------------- GEMM (FFMA2 + register double-buffer) + fused logits -------
template <int HEADS>
__global__ void __launch_bounds__(256, 2) gemm_kernel(const float* __restrict__ X,
                                                      const float* __restrict__ W,
                                                      float* __restrict__ O,
                                                      const float* __restrict__ asv,
                                                      const float* __restrict__ adv,
                                                      float* __restrict__ als,
                                                      float* __restrict__ ald, int n) {
    __shared__ float xs[32][132];          // [k][row]
    __shared__ float ws[32][128];          // [k][col]
    int tid = threadIdx.x;
    int base = blockIdx.x * 128;
    int tx = tid & 15, ty = tid >> 4;

    unsigned long long acc2[4][8];
#pragma unroll
    for (int p = 0; p < 4; p++)
#pragma unroll
        for (int j = 0; j < 8; j++) acc2[p][j] = 0ull;

    // per-thread load coordinates
    int wr[4], wc[4], xr[4], xc[4];
#pragma unroll
    for (int l = 0; l < 4; l++) {
        int idx = tid + l * 256;
        wr[l] = idx >> 5;          wc[l] = (idx & 31) << 2;
        xr[l] = idx >> 3;          xc[l] = (idx & 7) << 2;
    }

    // prefetch chunk 0
    float4 wv[4], xv[4];
#pragma unroll
    for (int l = 0; l < 4; l++) {
        wv[l] = *(const float4*)(W + (size_t)wr[l] * 128 + wc[l]);
        int node = base + xr[l];
        xv[l] = make_float4(0.f, 0.f, 0.f, 0.f);
        if (node < n) xv[l] = *(const float4*)(X + (size_t)node * 128 + xc[l]);
    }

    for (int kk = 0; kk < 128; kk += 32) {
        // store prefetched chunk to smem
#pragma unroll
        for (int l = 0; l < 4; l++) {
            *(float4*)&ws[wr[l]][wc[l]] = wv[l];
            float4 v = xv[l];
            int c = xc[l], r = xr[l];
            xs[c][r] = v.x; xs[c + 1][r] = v.y; xs[c + 2][r] = v.z; xs[c + 3][r] = v.w;
        }
        __syncthreads();
        // prefetch next chunk during compute
        if (kk + 32 < 128) {
#pragma unroll
            for (int l = 0; l < 4; l++) {
                wv[l] = *(const float4*)(W + (size_t)(kk + 32 + wr[l]) * 128 + wc[l]);
                int node = base + xr[l];
                xv[l] = make_float4(0.f, 0.f, 0.f, 0.f);
                if (node < n)
                    xv[l] = *(const float4*)(X + (size_t)node * 128 + kk + 32 + xc[l]);
            }
        }
#pragma unroll 8
        for (int k = 0; k < 32; k++) {
            ulonglong2 xa = *(const ulonglong2*)&xs[k][ty * 8];
            ulonglong2 xb = *(const ulonglong2*)&xs[k][ty * 8 + 4];
            unsigned long long xp[4] = {xa.x, xa.y, xb.x, xb.y};
            float4 wa = *(const float4*)&ws[k][tx * 8];
            float4 wb = *(const float4*)&ws[k][tx * 8 + 4];
            unsigned long long wp[8];
            wp[0] = pack2(wa.x, wa.x); wp[1] = pack2(wa.y, wa.y);
            wp[2] = pack2(wa.z, wa.z); wp[3] = pack2(wa.w, wa.w);
            wp[4] = pack2(wb.x, wb.x); wp[5] = pack2(wb.y, wb.y);
            wp[6] = pack2(wb.z, wb.z); wp[7] = pack2(wb.w, wb.w);
#pragma unroll
            for (int p = 0; p < 4; p++)
#pragma unroll
                for (int j = 0; j < 8; j++) fma2(acc2[p][j], xp[p], wp[j]);
        }
        __syncthreads();
    }

    float acc[8][8];
#pragma unroll
    for (int p = 0; p < 4; p++)
#pragma unroll
        for (int j = 0; j < 8; j++) {
            float2 f = *reinterpret_cast<float2*>(&acc2[p][j]);
            acc[2 * p][j] = f.x;
            acc[2 * p + 1][j] = f.y;
        }

    float av[8], dv[8];
#pragma unroll
    for (int j = 0; j < 8; j++) {
        av[j] = asv[tx * 8 + j];
        dv[j] = adv[tx * 8 + j];
    }
    const unsigned FULL = 0xffffffffu;
    int lane = tid & 31;

#pragma unroll
    for (int i = 0; i < 8; i++) {
        int node = base + ty * 8 + i;
        bool ok = node < n;
        if (ok) {
            *(float4*)(O + (size_t)node * 128 + tx * 8) =
                make_float4(acc[i][0], acc[i][1], acc[i][2], acc[i][3]);
            *(float4*)(O + (size_t)node * 128 + tx * 8 + 4) =
                make_float4(acc[i][4], acc[i][5], acc[i][6], acc[i][7]);
        }
        float s_ = 0.f, d_ = 0.f;
#pragma unroll
        for (int j = 0; j < 8; j++) {
            s_ = fmaf(acc[i][j], av[j], s_);
            d_ = fmaf(acc[i][j], dv[j], d_);
        }
        if (HEADS == 4) {
#pragma unroll
            for (int o = 1; o <= 2; o <<= 1) {
                s_ += __shfl_xor_sync(FULL, s_, o);
                d_ += __shfl_xor_sync(FULL, d_, o);
            }
            if ((lane & 3) == 0 && ok) {
                int h = tx >> 2;
                als[node * 4 + h] = s_;
                ald[node * 4 + h] = d_;
            }
        } else {
#pragma unroll
            for (int o = 1; o <= 8; o <<= 1) {
                s_ += __shfl_xor_sync(FULL, s_, o);
                d_ += __shfl_xor_sync(FULL, d_, o);
            }
            if ((lane & 15) == 0 && ok) {
                als[node] = s_;
                ald[node] = d_;
            }
        }
    }
}

// ---------------- warp-per-dst aggregation (smem-staged, FFMA2 — proven) -----
template <int HEADS, bool ELU>
__global__ void __launch_bounds__(256) agg_kernel(const float* __restrict__ Hm,
                                                  const float* __restrict__ als,
                                                  const float* __restrict__ ald,
                                                  const float* __restrict__ bias,
                                                  float* __restrict__ out, int n) {
    __shared__ int s_st[8][32];
    __shared__ float4 p_st4[8][32];
    __shared__ float p_st1[8][32];
    int wid = threadIdx.x >> 5;
    int lane = threadIdx.x & 31;
    int w = blockIdx.x * 8 + wid;
    if (w >= n) return;
    const unsigned FULL = 0xffffffffu;
    int beg = g_off[w], end = g_off[w + 1];
    int h0 = lane >> 3;

    if (HEADS == 4) {
        float4 ed4 = *(const float4*)(ald + w * 4);
        float dl0 = 0.f, dl1 = 0.f, dl2 = 0.f, dl3 = 0.f;
        unsigned long long acc01 = 0ull, acc23 = 0ull;

        for (int t0 = beg; t0 < end; t0 += 32) {
            int e = t0 + lane;
            bool v = e < end;
            int s = v ? g_srcs[e] : 0;
            float4 a4 = *(const float4*)(als + s * 4);
            float l0 = a4.x + ed4.x, l1 = a4.y + ed4.y, l2 = a4.z + ed4.z, l3 = a4.w + ed4.w;
            l0 = l0 > 0.f ? l0 : 0.2f * l0;
            l1 = l1 > 0.f ? l1 : 0.2f * l1;
            l2 = l2 > 0.f ? l2 : 0.2f * l2;
            l3 = l3 > 0.f ? l3 : 0.2f * l3;
            float p0 = v ? __expf(l0) : 0.f;
            float p1 = v ? __expf(l1) : 0.f;
            float p2 = v ? __expf(l2) : 0.f;
            float p3 = v ? __expf(l3) : 0.f;
            dl0 += p0; dl1 += p1; dl2 += p2; dl3 += p3;

            __syncwarp();
            s_st[wid][lane] = s;
            p_st4[wid][lane] = make_float4(p0, p1, p2, p3);
            __syncwarp();

            int cnt = end - t0; if (cnt > 32) cnt = 32;
            const float* pf = (const float*)&p_st4[wid][0];
#pragma unroll 2
            for (int t = 0; t < cnt; t++) {
                int st = s_st[wid][t];
                float pt = pf[t * 4 + h0];
                ulonglong2 hv = *(const ulonglong2*)(Hm + (size_t)st * 128 + lane * 4);
                unsigned long long pt2 = pack2(pt, pt);
                fma2(acc01, hv.x, pt2);
                fma2(acc23, hv.y, pt2);
            }
        }
#pragma unroll
        for (int o = 16; o > 0; o >>= 1) {
            dl0 += __shfl_xor_sync(FULL, dl0, o);
            dl1 += __shfl_xor_sync(FULL, dl1, o);
            dl2 += __shfl_xor_sync(FULL, dl2, o);
            dl3 += __shfl_xor_sync(FULL, dl3, o);
        }
        float den = h0 == 0 ? dl0 : (h0 == 1 ? dl1 : (h0 == 2 ? dl2 : dl3));
        float inv = 1.f / (den + 1e-16f);
        float2 a01 = *reinterpret_cast<float2*>(&acc01);
        float2 a23 = *reinterpret_cast<float2*>(&acc23);
        float4 bo = *(const float4*)(bias + lane * 4);
        float4 vo;
        vo.x = a01.x * inv + bo.x;
        vo.y = a01.y * inv + bo.y;
        vo.z = a23.x * inv + bo.z;
        vo.w = a23.y * inv + bo.w;
        if (ELU) {
            vo.x = vo.x > 0.f ? vo.x : expm1f(vo.x);
            vo.y = vo.y > 0.f ? vo.y : expm1f(vo.y);
            vo.z = vo.z > 0.f ? vo.z : expm1f(vo.z);
            vo.w = vo.w > 0.f ? vo.w : expm1f(vo.w);
        }
        *(float4*)(out + (size_t)w * 128 + lane * 4) = vo;
    } else {
        float ed = ald[w];
        float dl = 0.f;
        unsigned long long acc01 = 0ull, acc23 = 0ull;

        for (int t0 = beg; t0 < end; t0 += 32) {
            int e = t0 + lane;
            bool v = e < end;
            int s = v ? g_srcs[e] : 0;
            float lv = als[s] + ed;
            lv = lv > 0.f ? lv : 0.2f * lv;
            float p = v ? __expf(lv) : 0.f;
            dl += p;

            __syncwarp();
            s_st[wid][lane] = s;
            p_st1[wid][lane] = p;
            __syncwarp();

            int cnt = end - t0; if (cnt > 32) cnt = 32;
#pragma unroll 2
            for (int t = 0; t < cnt; t++) {
                int st = s_st[wid][t];
                float pt = p_st1[wid][t];
                ulonglong2 hv = *(const ulonglong2*)(Hm + (size_t)st * 128 + lane * 4);
                unsigned long long pt2 = pack2(pt, pt);
                fma2(acc01, hv.x, pt2);
                fma2(acc23, hv.y, pt2);
            }
        }
#pragma unroll
        for (int o = 16; o > 0; o >>= 1) dl += __shfl_xor_sync(FULL, dl, o);
        float inv = 1.f / (dl + 1e-16f);
        float2 a01 = *reinterpret_cast<float2*>(&acc01);
        float2 a23 = *reinterpret_cast<float2*>(&acc23);
        float4 bo = *(const float4*)(bias + lane * 4);
        float4 vo;
        vo.x = a01.x * inv + bo.x;
        vo.y = a01.y * inv + bo.y;
        vo.z = a23.x * inv + bo.z;
        vo.w = a23.y * inv + bo.w;
        *(float4*)(out + (size_t)w * 128 + lane * 4) = vo;
    }
}

// ---------------- host ----------------
extern "C" void kernel_launch(void* const* d_in, const int* in_sizes, int n_in,
                              void* d_out, int out_size) {
    const float* x       = (const float*)d_in[0];
    const void* ei       = d_in[1];
    const float* W1      = (const float*)d_in[2];
    const float* as1     = (const float*)d_in[3];
    const float* ad1     = (const float*)d_in[4];
    const float* b1      = (const float*)d_in[5];
    const float* W2      = (const float*)d_in[6];
    const float* as2     = (const float*)d_in[7];
    const float* ad2     = (const float*)d_in[8];
    const float* b2      = (const float*)d_in[9];
    float* out = (float*)d_out;

    int n = in_sizes[0] / 128;   // 50000
    int e = in_sizes[1] / 2;     // 600000

    float *p_h1, *p_x2, *p_h2, *p_als1, *p_ald1, *p_als2, *p_ald2;
    cudaGetSymbolAddress((void**)&p_h1, g_h1);
    cudaGetSymbolAddress((void**)&p_x2, g_x2);
    cudaGetSymbolAddress((void**)&p_h2, g_h2);
    cudaGetSymbolAddress((void**)&p_als1, g_als1);
    cudaGetSymbolAddress((void**)&p_ald1, g_ald1);
    cudaGetSymbolAddress((void**)&p_als2, g_als2);
    cudaGetSymbolAddress((void**)&p_ald2, g_ald2);

    int nb = (n + SCAN_CHUNK - 1) / SCAN_CHUNK;   // 49
    int G = (n + 127) / 128;                      // 391
    int warp_blocks = (n + 7) / 8;

    hist_kernel<<<(e + 255) / 256, 256>>>(ei, e);
    scan_kernel<<<nb, 256>>>(n, nb);
    scatter_kernel<<<(e + n + 255) / 256, 256>>>(ei, e, n);

    // ----- layer 1 -----
    gemm_kernel<4><<<G, 256>>>(x, W1, p_h1, as1, ad1, p_als1, p_ald1, n);
    agg_kernel<4, true><<<warp_blocks, 256>>>(p_h1, p_als1, p_ald1, b1, p_x2, n);

    // ----- layer 2 -----
    gemm_kernel<1><<<G, 256>>>(p_x2, W2, p_h2, as2, ad2, p_als2, p_ald2, n);
    agg_kernel<1, false><<<warp_blocks, 256>>>(p_h2, p_als2, p_ald2, b2, out, n);
}

// round 12
// speedup vs baseline: 1.0776x; 1.0776x over previous
#include <cuda_runtime.h>
#include <cuda_bf16.h>
#include <math.h>

#define NN 50000
#define EE 600000
#define ET (EE + NN)
#define SCAN_CHUNK 1024
#define NB_SCAN ((NN + SCAN_CHUNK - 1) / SCAN_CHUNK)   // 49
#define FLAG_AGG  (1 << 30)
#define FLAG_INC  (1u << 31)
#define FLAG_MASK ((1 << 30) - 1)

// ---------------- scratch (module-load zeroed; invariants restored per call) --
__device__ int g_cnt[NN];
__device__ int g_cur[NN];
__device__ int g_off[NN + 1];
__device__ int g_flagw[NB_SCAN];
__device__ int g_srcs[ET];
__device__ __align__(16) float g_h1[(size_t)NN * 128];
__device__ __align__(16) float g_x2[(size_t)NN * 128];
__device__ __align__(16) float g_h2[(size_t)NN * 128];
__device__ __align__(16) float g_als1[NN * 4];
__device__ __align__(16) float g_ald1[NN * 4];
__device__ float g_als2[NN];
__device__ float g_ald2[NN];

__device__ __forceinline__ int load_idx(const void* p, size_t i, int is64) {
    if (is64) return (int)((const long long*)p)[i];
    return ((const int*)p)[i];
}

__device__ __forceinline__ int detect_is64_block(const long long* ei64, int e) {
    __shared__ int s_ok;
    if (threadIdx.x == 0) s_ok = 1;
    __syncthreads();
    if (threadIdx.x < 64) {
        long long v = ei64[threadIdx.x];
        long long v2 = ei64[(size_t)e + threadIdx.x];
        if (v < 0 || v >= NN || v2 < 0 || v2 >= NN) s_ok = 0;
    }
    __syncthreads();
    return s_ok;
}

// ---------------- f32x2 helpers ----------------
__device__ __forceinline__ unsigned long long pack2(float lo, float hi) {
    unsigned long long r;
    asm("mov.b64 %0, {%1, %2};" : "=l"(r) : "f"(lo), "f"(hi));
    return r;
}
__device__ __forceinline__ void fma2(unsigned long long& d, unsigned long long a,
                                     unsigned long long b) {
    asm("fma.rn.f32x2 %0, %1, %2, %0;" : "+l"(d) : "l"(a), "l"(b));
}

// ---------------- CSR: histogram (also clears scan flags) ----------
__global__ void hist_kernel(const void* __restrict__ ei, int e) {
    if (blockIdx.x < NB_SCAN && threadIdx.x == 0) g_flagw[blockIdx.x] = 0;
    int is64 = detect_is64_block((const long long*)ei, e);
    int i = blockIdx.x * blockDim.x + threadIdx.x;
    if (i < e) {
        int d = load_idx(ei, (size_t)e + i, is64);
        if (d >= 0 && d < NN) atomicAdd(&g_cnt[d], 1);
    }
}

// ---------------- CSR: single-pass decoupled-lookback scan -------------------
__global__ void __launch_bounds__(256) scan_kernel(int n, int nb) {
    int b = blockIdx.x, tid = threadIdx.x;
    int lane = tid & 31, wid = tid >> 5;
    int base = b * SCAN_CHUNK + tid * 4;
    int v[4];
    int tsum = 0;
#pragma unroll
    for (int k = 0; k < 4; k++) {
        int i = base + k;
        if (i < n) {
            v[k] = g_cnt[i] + 1;
            g_cnt[i] = 0;
            g_cur[i] = 0;
        } else v[k] = 0;
        tsum += v[k];
    }
    const unsigned FULL = 0xffffffffu;
    int x = tsum;
#pragma unroll
    for (int o = 1; o < 32; o <<= 1) {
        int y = __shfl_up_sync(FULL, x, o);
        if (lane >= o) x += y;
    }
    __shared__ int wsum[8];
    if (lane == 31) wsum[wid] = x;
    __syncthreads();
    __shared__ int s_excl;
    if (tid == 0) {
        int tot = 0;
#pragma unroll
        for (int w = 0; w < 8; w++) tot += wsum[w];
        if (b == 0) {
            *(volatile int*)&g_flagw[0] = tot | FLAG_INC;
            s_excl = 0;
            if (nb == 1) g_off[n] = tot;
        } else {
            *(volatile int*)&g_flagw[b] = (tot & FLAG_MASK) | FLAG_AGG;
            int excl = 0;
            for (int j = b - 1; j >= 0;) {
                int f;
                do { f = *(volatile int*)&g_flagw[j]; } while (f == 0);
                if (f & FLAG_INC) { excl += f & FLAG_MASK; break; }
                excl += f & FLAG_MASK;
                j--;
            }
            *(volatile int*)&g_flagw[b] = ((excl + tot) & FLAG_MASK) | FLAG_INC;
            s_excl = excl;
            if (b == nb - 1) g_off[n] = excl + tot;
        }
    }
    __syncthreads();
    int wpre = 0;
    for (int w = 0; w < wid; w++) wpre += wsum[w];
    int run = s_excl + wpre + (x - tsum);
#pragma unroll
    for (int k = 0; k < 4; k++) {
        int i = base + k;
        if (i < n) g_off[i] = run;
        run += v[k];
    }
}

// ---------------- CSR: scatter ----------------
__global__ void scatter_kernel(const void* __restrict__ ei, int e, int n) {
    int is64 = detect_is64_block((const long long*)ei, e);
    int i = blockIdx.x * blockDim.x + threadIdx.x;
    if (i < e) {
        int d = load_idx(ei, (size_t)e + i, is64);
        int s = load_idx(ei, (size_t)i, is64);
        if (d >= 0 && d < NN && s >= 0 && s < NN) {
            int pos = g_off[d] + atomicAdd(&g_cur[d], 1);
            g_srcs[pos] = s;
        }
    } else if (i < e + n) {
        int v = i - e;
        int pos = g_off[v] + atomicAdd(&g_cur[v], 1);
        g_srcs[pos] = v;
    }
}

// ---------------- GEMM: 64x128 tile, thread = 8 rows x 4 cols (FFMA2) --------
// warp = one ty (rows ty*8..+7), lane = tx (cols tx*4..+3)
template <int HEADS>
__global__ void __launch_bounds__(256, 3) gemm_kernel(const float* __restrict__ X,
                                                      const float* __restrict__ W,
                                                      float* __restrict__ O,
                                                      const float* __restrict__ asv,
                                                      const float* __restrict__ adv,
                                                      float* __restrict__ als,
                                                      float* __restrict__ ald, int n) {
    __shared__ float xs[32][68];           // [k][row]  (64 rows + pad)
    __shared__ float ws[32][128];          // [k][col]
    int tid = threadIdx.x;
    int base = blockIdx.x * 64;
    int tx = tid & 31, ty = tid >> 5;      // tx 0..31 (lane), ty 0..7 (warp)

    unsigned long long acc2[4][4];         // [rowpair][col]
#pragma unroll
    for (int p = 0; p < 4; p++)
#pragma unroll
        for (int j = 0; j < 4; j++) acc2[p][j] = 0ull;

    for (int kk = 0; kk < 128; kk += 32) {
        // W chunk: 32x128 = 1024 float4, 4 per thread
#pragma unroll
        for (int l = 0; l < 4; l++) {
            int idx = tid + l * 256;
            int r = idx >> 5;
            int c = (idx & 31) << 2;
            *(float4*)&ws[r][c] = *(const float4*)(W + (size_t)(kk + r) * 128 + c);
        }
        // X chunk transposed: 64 rows x 32 k = 512 float4, 2 per thread
#pragma unroll
        for (int l = 0; l < 2; l++) {
            int idx = tid + l * 256;       // 0..511
            int r = idx >> 3;              // 0..63
            int c = (idx & 7) << 2;        // 0..28
            int node = base + r;
            float4 v = make_float4(0.f, 0.f, 0.f, 0.f);
            if (node < n) v = *(const float4*)(X + (size_t)node * 128 + kk + c);
            xs[c][r] = v.x; xs[c + 1][r] = v.y; xs[c + 2][r] = v.z; xs[c + 3][r] = v.w;
        }
        __syncthreads();
#pragma unroll 8
        for (int k = 0; k < 32; k++) {
            // 8 rows (warp-broadcast: same address for all lanes)
            ulonglong2 xa = *(const ulonglong2*)&xs[k][ty * 8];
            ulonglong2 xb = *(const ulonglong2*)&xs[k][ty * 8 + 4];
            unsigned long long xp[4] = {xa.x, xa.y, xb.x, xb.y};
            // 4 cols, broadcast-packed
            float4 wa = *(const float4*)&ws[k][tx * 4];
            unsigned long long wp[4];
            wp[0] = pack2(wa.x, wa.x); wp[1] = pack2(wa.y, wa.y);
            wp[2] = pack2(wa.z, wa.z); wp[3] = pack2(wa.w, wa.w);
#pragma unroll
            for (int p = 0; p < 4; p++)
#pragma unroll
                for (int j = 0; j < 4; j++) fma2(acc2[p][j], xp[p], wp[j]);
        }
        __syncthreads();
    }

    float acc[8][4];
#pragma unroll
    for (int p = 0; p < 4; p++)
#pragma unroll
        for (int j = 0; j < 4; j++) {
            float2 f = *reinterpret_cast<float2*>(&acc2[p][j]);
            acc[2 * p][j] = f.x;
            acc[2 * p + 1][j] = f.y;
        }

    float av[4], dv[4];
#pragma unroll
    for (int j = 0; j < 4; j++) {
        av[j] = asv[tx * 4 + j];
        dv[j] = adv[tx * 4 + j];
    }
    const unsigned FULL = 0xffffffffu;

#pragma unroll
    for (int i = 0; i < 8; i++) {
        int node = base + ty * 8 + i;
        bool ok = node < n;
        if (ok) {
            *(float4*)(O + (size_t)node * 128 + tx * 4) =
                make_float4(acc[i][0], acc[i][1], acc[i][2], acc[i][3]);
        }
        float s_ = 0.f, d_ = 0.f;
#pragma unroll
        for (int j = 0; j < 4; j++) {
            s_ = fmaf(acc[i][j], av[j], s_);
            d_ = fmaf(acc[i][j], dv[j], d_);
        }
        if (HEADS == 4) {
            // head = tx>>3 ; reduce over the 8 lanes of that head
#pragma unroll
            for (int o = 1; o <= 4; o <<= 1) {
                s_ += __shfl_xor_sync(FULL, s_, o);
                d_ += __shfl_xor_sync(FULL, d_, o);
            }
            if ((tx & 7) == 0 && ok) {
                int h = tx >> 3;
                als[node * 4 + h] = s_;
                ald[node * 4 + h] = d_;
            }
        } else {
#pragma unroll
            for (int o = 1; o <= 16; o <<= 1) {
                s_ += __shfl_xor_sync(FULL, s_, o);
                d_ += __shfl_xor_sync(FULL, d_, o);
            }
            if (tx == 0 && ok) {
                als[node] = s_;
                ald[node] = d_;
            }
        }
    }
}

// ---------------- warp-per-dst aggregation (smem-staged, FFMA2 — proven) -----
template <int HEADS, bool ELU>
__global__ void __launch_bounds__(256) agg_kernel(const float* __restrict__ Hm,
                                                  const float* __restrict__ als,
                                                  const float* __restrict__ ald,
                                                  const float* __restrict__ bias,
                                                  float* __restrict__ out, int n) {
    __shared__ int s_st[8][32];
    __shared__ float4 p_st4[8][32];
    __shared__ float p_st1[8][32];
    int wid = threadIdx.x >> 5;
    int lane = threadIdx.x & 31;
    int w = blockIdx.x * 8 + wid;
    if (w >= n) return;
    const unsigned FULL = 0xffffffffu;
    int beg = g_off[w], end = g_off[w + 1];
    int h0 = lane >> 3;

    if (HEADS == 4) {
        float4 ed4 = *(const float4*)(ald + w * 4);
        float dl0 = 0.f, dl1 = 0.f, dl2 = 0.f, dl3 = 0.f;
        unsigned long long acc01 = 0ull, acc23 = 0ull;

        for (int t0 = beg; t0 < end; t0 += 32) {
            int e = t0 + lane;
            bool v = e < end;
            int s = v ? g_srcs[e] : 0;
            float4 a4 = *(const float4*)(als + s * 4);
            float l0 = a4.x + ed4.x, l1 = a4.y + ed4.y, l2 = a4.z + ed4.z, l3 = a4.w + ed4.w;
            l0 = l0 > 0.f ? l0 : 0.2f * l0;
            l1 = l1 > 0.f ? l1 : 0.2f * l1;
            l2 = l2 > 0.f ? l2 : 0.2f * l2;
            l3 = l3 > 0.f ? l3 : 0.2f * l3;
            float p0 = v ? __expf(l0) : 0.f;
            float p1 = v ? __expf(l1) : 0.f;
            float p2 = v ? __expf(l2) : 0.f;
            float p3 = v ? __expf(l3) : 0.f;
            dl0 += p0; dl1 += p1; dl2 += p2; dl3 += p3;

            __syncwarp();
            s_st[wid][lane] = s;
            p_st4[wid][lane] = make_float4(p0, p1, p2, p3);
            __syncwarp();

            int cnt = end - t0; if (cnt > 32) cnt = 32;
            const float* pf = (const float*)&p_st4[wid][0];
#pragma unroll 2
            for (int t = 0; t < cnt; t++) {
                int st = s_st[wid][t];
                float pt = pf[t * 4 + h0];
                ulonglong2 hv = *(const ulonglong2*)(Hm + (size_t)st * 128 + lane * 4);
                unsigned long long pt2 = pack2(pt, pt);
                fma2(acc01, hv.x, pt2);
                fma2(acc23, hv.y, pt2);
            }
        }
#pragma unroll
        for (int o = 16; o > 0; o >>= 1) {
            dl0 += __shfl_xor_sync(FULL, dl0, o);
            dl1 += __shfl_xor_sync(FULL, dl1, o);
            dl2 += __shfl_xor_sync(FULL, dl2, o);
            dl3 += __shfl_xor_sync(FULL, dl3, o);
        }
        float den = h0 == 0 ? dl0 : (h0 == 1 ? dl1 : (h0 == 2 ? dl2 : dl3));
        float inv = 1.f / (den + 1e-16f);
        float2 a01 = *reinterpret_cast<float2*>(&acc01);
        float2 a23 = *reinterpret_cast<float2*>(&acc23);
        float4 bo = *(const float4*)(bias + lane * 4);
        float4 vo;
        vo.x = a01.x * inv + bo.x;
        vo.y = a01.y * inv + bo.y;
        vo.z = a23.x * inv + bo.z;
        vo.w = a23.y * inv + bo.w;
        if (ELU) {
            vo.x = vo.x > 0.f ? vo.x : expm1f(vo.x);
            vo.y = vo.y > 0.f ? vo.y : expm1f(vo.y);
            vo.z = vo.z > 0.f ? vo.z : expm1f(vo.z);
            vo.w = vo.w > 0.f ? vo.w : expm1f(vo.w);
        }
        *(float4*)(out + (size_t)w * 128 + lane * 4) = vo;
    } else {
        float ed = ald[w];
        float dl = 0.f;
        unsigned long long acc01 = 0ull, acc23 = 0ull;

        for (int t0 = beg; t0 < end; t0 += 32) {
            int e = t0 + lane;
            bool v = e < end;
            int s = v ? g_srcs[e] : 0;
            float lv = als[s] + ed;
            lv = lv > 0.f ? lv : 0.2f * lv;
            float p = v ? __expf(lv) : 0.f;
            dl += p;

            __syncwarp();
            s_st[wid][lane] = s;
            p_st1[wid][lane] = p;
            __syncwarp();

            int cnt = end - t0; if (cnt > 32) cnt = 32;
#pragma unroll 2
            for (int t = 0; t < cnt; t++) {
                int st = s_st[wid][t];
                float pt = p_st1[wid][t];
                ulonglong2 hv = *(const ulonglong2*)(Hm + (size_t)st * 128 + lane * 4);
                unsigned long long pt2 = pack2(pt, pt);
                fma2(acc01, hv.x, pt2);
                fma2(acc23, hv.y, pt2);
            }
        }
#pragma unroll
        for (int o = 16; o > 0; o >>= 1) dl += __shfl_xor_sync(FULL, dl, o);
        float inv = 1.f / (dl + 1e-16f);
        float2 a01 = *reinterpret_cast<float2*>(&acc01);
        float2 a23 = *reinterpret_cast<float2*>(&acc23);
        float4 bo = *(const float4*)(bias + lane * 4);
        float4 vo;
        vo.x = a01.x * inv + bo.x;
        vo.y = a01.y * inv + bo.y;
        vo.z = a23.x * inv + bo.z;
        vo.w = a23.y * inv + bo.w;
        *(float4*)(out + (size_t)w * 128 + lane * 4) = vo;
    }
}

// ---------------- host ----------------
extern "C" void kernel_launch(void* const* d_in, const int* in_sizes, int n_in,
                              void* d_out, int out_size) {
    const float* x       = (const float*)d_in[0];
    const void* ei       = d_in[1];
    const float* W1      = (const float*)d_in[2];
    const float* as1     = (const float*)d_in[3];
    const float* ad1     = (const float*)d_in[4];
    const float* b1      = (const float*)d_in[5];
    const float* W2      = (const float*)d_in[6];
    const float* as2     = (const float*)d_in[7];
    const float* ad2     = (const float*)d_in[8];
    const float* b2      = (const float*)d_in[9];
    float* out = (float*)d_out;

    int n = in_sizes[0] / 128;   // 50000
    int e = in_sizes[1] / 2;     // 600000

    float *p_h1, *p_x2, *p_h2, *p_als1, *p_ald1, *p_als2, *p_ald2;
    cudaGetSymbolAddress((void**)&p_h1, g_h1);
    cudaGetSymbolAddress((void**)&p_x2, g_x2);
    cudaGetSymbolAddress((void**)&p_h2, g_h2);
    cudaGetSymbolAddress((void**)&p_als1, g_als1);
    cudaGetSymbolAddress((void**)&p_ald1, g_ald1);
    cudaGetSymbolAddress((void**)&p_als2, g_als2);
    cudaGetSymbolAddress((void**)&p_ald2, g_ald2);

    int nb = (n + SCAN_CHUNK - 1) / SCAN_CHUNK;   // 49
    int G = (n + 63) / 64;                        // 782
    int warp_blocks = (n + 7) / 8;

    hist_kernel<<<(e + 255) / 256, 256>>>(ei, e);
    scan_kernel<<<nb, 256>>>(n, nb);
    scatter_kernel<<<(e + n + 255) / 256, 256>>>(ei, e, n);

    // ----- layer 1 -----
    gemm_kernel<4><<<G, 256>>>(x, W1, p_h1, as1, ad1, p_als1, p_ald1, n);
    agg_kernel<4, true><<<warp_blocks, 256>>>(p_h1, p_als1, p_ald1, b1, p_x2, n);

    // ----- layer 2 -----
    gemm_kernel<1><<<G, 256>>>(p_x2, W2, p_h2, as2, ad2, p_als2, p_ald2, n);
    agg_kernel<1, false><<<warp_blocks, 256>>>(p_h2, p_als2, p_ald2, b2, out, n);
}